// round 1
// baseline (speedup 1.0000x reference)
#include <cuda_runtime.h>

// QCNN_58025008169535
// x: [32,128,128,3] f32, w: [4,4,3] f32 -> out: [32, 127*127, 4] f32
//
// Strategy:
//  - Kernel 1 (16 threads): fold the whole variational circuit (4 layers of
//    Rz*Ry*Rx per qubit + CZ ladder) into one 16x16 complex unitary U by
//    evolving the 16 basis states. Depends only on w.
//  - Kernel 2 (1 thread / patch): build the encoded product state
//    (per qubit (cos(pi*l1/2), sin(pi*l1/2)*e^{i*pi*l2}); l0 is a global
//    phase and is dropped), apply U (16x16 complex matvec, U broadcast from
//    shared memory), accumulate signed |amp|^2 into the 4 <Z_i> outputs.

#define DIM 16
#define NL 4
#define NQ 4

static constexpr int Bc = 32, Hc = 128, Wc = 128;
static constexpr int PHc = Hc - 1, PWc = Wc - 1;
static constexpr int Pc = PHc * PWc;          // 16129
static constexpr int TOTALc = Bc * Pc;        // 516128

__device__ float2 g_U[DIM * DIM];             // row-major U[s][t]

__device__ __forceinline__ float2 cmul(float2 a, float2 b) {
    return make_float2(fmaf(a.x, b.x, -a.y * b.y), fmaf(a.x, b.y, a.y * b.x));
}
__device__ __forceinline__ float2 cadd(float2 a, float2 b) {
    return make_float2(a.x + b.x, a.y + b.y);
}

// ---------------------------------------------------------------------------
// Kernel 1: build the monolithic variational unitary. Thread t evolves basis
// state e_t; writes column t of U. All state-array indices are compile-time
// constants after unrolling -> register resident.
// ---------------------------------------------------------------------------
__global__ void k_build_U(const float* __restrict__ w) {
    int t = threadIdx.x;
    if (t >= DIM) return;

    float2 a[DIM];
#pragma unroll
    for (int s = 0; s < DIM; s++) a[s] = make_float2((s == t) ? 1.f : 0.f, 0.f);

#pragma unroll
    for (int h = 0; h < NL; h++) {
#pragma unroll
        for (int q = 0; q < NQ; q++) {
            float wx = w[(h * NQ + q) * 3 + 0];
            float wy = w[(h * NQ + q) * 3 + 1];
            float wz = w[(h * NQ + q) * 3 + 2];
            float cx, sx, cy, sy, cz, sz;
            sincosf(0.5f * wx, &sx, &cx);
            sincosf(0.5f * wy, &sy, &cy);
            sincosf(0.5f * wz, &sz, &cz);
            // Ry(wy)*Rx(wx):
            //   Rx = [[cx, -i sx], [-i sx, cx]], Ry = [[cy, -sy], [sy, cy]]
            float2 m00 = make_float2(cy * cx,  sy * sx);
            float2 m01 = make_float2(-sy * cx, -cy * sx);
            float2 m10 = make_float2(sy * cx,  -cy * sx);
            float2 m11 = make_float2(cy * cx,  -sy * sx);
            // Rz(wz): row0 *= e^{-i wz/2}, row1 *= e^{+i wz/2}
            float2 e0 = make_float2(cz, -sz);
            float2 e1 = make_float2(cz,  sz);
            float2 u00 = cmul(e0, m00), u01 = cmul(e0, m01);
            float2 u10 = cmul(e1, m10), u11 = cmul(e1, m11);

            const int msk = 8 >> q;   // qubit q lives at bit (3-q)
#pragma unroll
            for (int s = 0; s < DIM; s++) {
                if ((s & msk) == 0) {
                    float2 p0 = a[s], p1 = a[s + msk];
                    a[s]       = cadd(cmul(u00, p0), cmul(u01, p1));
                    a[s + msk] = cadd(cmul(u10, p0), cmul(u11, p1));
                }
            }
        }
        // CZ(0,1): bits {3,2}; CZ(2,3): bits {1,0}; CZ(1,2): bits {2,1}
#pragma unroll
        for (int s = 0; s < DIM; s++) {
            bool neg = (((s & 12) == 12) ^ ((s & 3) == 3)) ^ ((s & 6) == 6);
            if (neg) { a[s].x = -a[s].x; a[s].y = -a[s].y; }
        }
    }

#pragma unroll
    for (int s = 0; s < DIM; s++) g_U[s * DIM + t] = a[s];
}

// ---------------------------------------------------------------------------
// Kernel 2: one thread per patch.
// ---------------------------------------------------------------------------
__global__ void __launch_bounds__(256)
k_qcnn(const float* __restrict__ x, float* __restrict__ out) {
    __shared__ float4 sU[DIM * DIM / 2];   // 16x16 float2 as 128 float4
    {
        const float4* u4 = reinterpret_cast<const float4*>(g_U);
        for (int i = threadIdx.x; i < DIM * DIM / 2; i += 256) sU[i] = u4[i];
    }
    __syncthreads();

    int idx = blockIdx.x * 256 + threadIdx.x;
    if (idx >= TOTALc) return;

    int b  = idx / Pc;
    int p  = idx - b * Pc;
    int ph = p / PWc;
    int pw = p - ph * PWc;

    // Encoding: per qubit n (pixel (ph+dy, pw+dx), dy=n>>1, dx=n&1):
    //   amp0 = cos(pi*l1/2), amp1 = sin(pi*l1/2) * e^{i*pi*l2}
    float  cth[NQ];
    float2 eph[NQ];
#pragma unroll
    for (int n = 0; n < NQ; n++) {
        int dy = n >> 1, dx = n & 1;
        const float* px = x + ((((b * Hc) + (ph + dy)) * Wc + (pw + dx)) * 3);
        float l1 = px[1];
        float l2 = px[2];
        float sb, cb, sp, cp;
        sincosf(1.57079632679489662f * l1, &sb, &cb);
        sincosf(3.14159265358979323f * l2, &sp, &cp);
        cth[n] = cb;
        eph[n] = make_float2(sb * cp, sb * sp);
    }

    // psi[s], s = t0*8 + t1*4 + t2*2 + t3 (C-order of the (2,2,2,2) tensor)
    float2 ab[4], cd[4];
    ab[0] = make_float2(cth[0] * cth[1], 0.f);
    ab[1] = make_float2(cth[0] * eph[1].x, cth[0] * eph[1].y);
    ab[2] = make_float2(eph[0].x * cth[1], eph[0].y * cth[1]);
    ab[3] = cmul(eph[0], eph[1]);
    cd[0] = make_float2(cth[2] * cth[3], 0.f);
    cd[1] = make_float2(cth[2] * eph[3].x, cth[2] * eph[3].y);
    cd[2] = make_float2(eph[2].x * cth[3], eph[2].y * cth[3]);
    cd[3] = cmul(eph[2], eph[3]);

    float2 psi[16];
#pragma unroll
    for (int i = 0; i < 4; i++)
#pragma unroll
        for (int j = 0; j < 4; j++)
            psi[i * 4 + j] = cmul(ab[i], cd[j]);

    // psi' = U psi;   z_i = sum_s sign_i(s) * |psi'_s|^2
    float z0 = 0.f, z1 = 0.f, z2 = 0.f, z3 = 0.f;
#pragma unroll
    for (int s = 0; s < DIM; s++) {
        float ar0 = 0.f, ai0 = 0.f, ar1 = 0.f, ai1 = 0.f;
#pragma unroll
        for (int k = 0; k < 8; k++) {
            float4 u = sU[s * 8 + k];          // U[s][2k], U[s][2k+1]
            float2 pa = psi[2 * k];
            float2 pb = psi[2 * k + 1];
            ar0 = fmaf(u.x, pa.x, ar0); ar0 = fmaf(-u.y, pa.y, ar0);
            ai0 = fmaf(u.x, pa.y, ai0); ai0 = fmaf( u.y, pa.x, ai0);
            ar1 = fmaf(u.z, pb.x, ar1); ar1 = fmaf(-u.w, pb.y, ar1);
            ai1 = fmaf(u.z, pb.y, ai1); ai1 = fmaf( u.w, pb.x, ai1);
        }
        float ar = ar0 + ar1;
        float ai = ai0 + ai1;
        float pr = fmaf(ar, ar, ai * ai);
        z0 += (s & 8) ? -pr : pr;
        z1 += (s & 4) ? -pr : pr;
        z2 += (s & 2) ? -pr : pr;
        z3 += (s & 1) ? -pr : pr;
    }

    reinterpret_cast<float4*>(out)[idx] = make_float4(z0, z1, z2, z3);
}

extern "C" void kernel_launch(void* const* d_in, const int* in_sizes, int n_in,
                              void* d_out, int out_size) {
    const float* x = (const float*)d_in[0];
    const float* w = (const float*)d_in[1];
    float* out = (float*)d_out;

    k_build_U<<<1, 32>>>(w);

    int blocks = (TOTALc + 255) / 256;   // 2017
    k_qcnn<<<blocks, 256>>>(x, out);
}

// round 3
// speedup vs baseline: 1.2061x; 1.2061x over previous
#include <cuda_runtime.h>

// QCNN_58025008169535
// x: [32,128,128,3] f32, w: [4,4,3] f32 -> out: [32, 127*127, 4] f32

#define DIM 16
#define NL 4
#define NQ 4

static constexpr int Bc = 32, Hc = 128, Wc = 128;
static constexpr int PHc = Hc - 1, PWc = Wc - 1;
static constexpr int Pc = PHc * PWc;          // 16129
static constexpr int TOTALc = Bc * Pc;        // 516128

typedef unsigned long long ull;

// Packed U: for column k, state s: (re,re) and (-im,im) of U[s][k]
__device__ ulonglong2 g_Upk[DIM * DIM];

__device__ __forceinline__ float2 cmul(float2 a, float2 b) {
    return make_float2(fmaf(a.x, b.x, -a.y * b.y), fmaf(a.x, b.y, a.y * b.x));
}
__device__ __forceinline__ float2 cadd(float2 a, float2 b) {
    return make_float2(a.x + b.x, a.y + b.y);
}
__device__ __forceinline__ ull pk2(float lo, float hi) {
    ull r; asm("mov.b64 %0, {%1,%2};" : "=l"(r) : "f"(lo), "f"(hi)); return r;
}
__device__ __forceinline__ void upk2(ull v, float& lo, float& hi) {
    asm("mov.b64 {%0,%1}, %2;" : "=f"(lo), "=f"(hi) : "l"(v));
}
__device__ __forceinline__ ull ffma2(ull a, ull b, ull c) {
    ull d; asm("fma.rn.f32x2 %0, %1, %2, %3;" : "=l"(d) : "l"(a), "l"(b), "l"(c));
    return d;
}

// ---------------------------------------------------------------------------
// Kernel 1 (256 threads): build the variational unitary in parallel.
//   stage 0: 16 threads -> 16 single-qubit gates (Rz*Ry*Rx)
//   stage 1: layer matrices M_h = CZsigns * (g0 x g1 x g2 x g3), elementwise
//   stage 2: T1 = M2*M1, T2 = M4*M3  (256 parallel dot-16)
//   stage 3: U  = T2*T1, write packed layout
// ---------------------------------------------------------------------------
__global__ void k_build_U(const float* __restrict__ w) {
    __shared__ float2 sg[16][4];         // gate (h*4+q): u00,u01,u10,u11
    __shared__ float2 sM[4][DIM][DIM];   // layer matrices (CZ folded)
    __shared__ float2 sT[2][DIM][DIM];

    int tid = threadIdx.x;

    if (tid < 16) {
        float wx = w[tid * 3 + 0];
        float wy = w[tid * 3 + 1];
        float wz = w[tid * 3 + 2];
        float cx, sx, cy, sy, cz, sz;
        sincosf(0.5f * wx, &sx, &cx);
        sincosf(0.5f * wy, &sy, &cy);
        sincosf(0.5f * wz, &sz, &cz);
        // Ry(wy)*Rx(wx)
        float2 m00 = make_float2(cy * cx,  sy * sx);
        float2 m01 = make_float2(-sy * cx, -cy * sx);
        float2 m10 = make_float2(sy * cx,  -cy * sx);
        float2 m11 = make_float2(cy * cx,  -sy * sx);
        // Rz(wz) on rows
        float2 e0 = make_float2(cz, -sz);
        float2 e1 = make_float2(cz,  sz);
        sg[tid][0] = cmul(e0, m00);
        sg[tid][1] = cmul(e0, m01);
        sg[tid][2] = cmul(e1, m10);
        sg[tid][3] = cmul(e1, m11);
    }
    __syncthreads();

    // Layer matrices: 1024 elements, 4 per thread
#pragma unroll
    for (int r = 0; r < 4; r++) {
        int e = tid + 256 * r;
        int h = e >> 8;
        int st = e & 255;
        int s = st >> 4, t = st & 15;
        float2 prod = make_float2(1.f, 0.f);
#pragma unroll
        for (int q = 0; q < NQ; q++) {
            int sb = (s >> (3 - q)) & 1;
            int tb = (t >> (3 - q)) & 1;
            prod = cmul(prod, sg[h * 4 + q][sb * 2 + tb]);
        }
        // CZ(0,1), CZ(2,3), CZ(1,2) combined diagonal sign on output row s
        bool neg = (((s & 12) == 12) ^ ((s & 3) == 3)) ^ ((s & 6) == 6);
        if (neg) { prod.x = -prod.x; prod.y = -prod.y; }
        sM[h][s][t] = prod;
    }
    __syncthreads();

    {
        int s = tid >> 4, t = tid & 15;
        float2 a1 = make_float2(0.f, 0.f);
        float2 a2 = make_float2(0.f, 0.f);
#pragma unroll
        for (int k = 0; k < DIM; k++) {
            a1 = cadd(a1, cmul(sM[1][s][k], sM[0][k][t]));
            a2 = cadd(a2, cmul(sM[3][s][k], sM[2][k][t]));
        }
        sT[0][s][t] = a1;
        sT[1][s][t] = a2;
    }
    __syncthreads();

    {
        int s = tid >> 4, t = tid & 15;
        float2 u = make_float2(0.f, 0.f);
#pragma unroll
        for (int k = 0; k < DIM; k++)
            u = cadd(u, cmul(sT[1][s][k], sT[0][k][t]));
        // packed: column-major [k][s], (re,re) and (-im,im)
        ulonglong2 pkd;
        pkd.x = pk2(u.x, u.x);
        pkd.y = pk2(-u.y, u.y);
        g_Upk[t * DIM + s] = pkd;
    }
}

// ---------------------------------------------------------------------------
// Kernel 2: one thread per patch, FFMA2 matvec.
// ---------------------------------------------------------------------------
__global__ void __launch_bounds__(256, 3)
k_qcnn(const float* __restrict__ x, float* __restrict__ out) {
    __shared__ ulonglong2 sU[DIM * DIM];   // [k][s] packed (re,re | -im,im), 4KB
    sU[threadIdx.x] = g_Upk[threadIdx.x];
    __syncthreads();

    int idx = blockIdx.x * 256 + threadIdx.x;
    if (idx >= TOTALc) return;

    int b  = idx / Pc;
    int p  = idx - b * Pc;
    int ph = p / PWc;
    int pw = p - ph * PWc;

    // Encoding: per qubit n (pixel (ph+dy, pw+dx)):
    //   amp0 = cos(pi*l1/2), amp1 = sin(pi*l1/2) * e^{i*pi*l2}  (l0 = global phase)
    float  cth[NQ];
    float2 eph[NQ];
#pragma unroll
    for (int n = 0; n < NQ; n++) {
        int dy = n >> 1, dx = n & 1;
        const float* px = x + ((((b * Hc) + (ph + dy)) * Wc + (pw + dx)) * 3);
        float l1 = px[1];
        float l2 = px[2];
        float sb, cb, sp, cp;
        sincosf(1.57079632679489662f * l1, &sb, &cb);
        sincosf(3.14159265358979323f * l2, &sp, &cp);
        cth[n] = cb;
        eph[n] = make_float2(sb * cp, sb * sp);
    }

    // psi = ab (qubits 0,1) x cd (qubits 2,3);  s = i*4 + j
    float2 ab[4], cd[4];
    ab[0] = make_float2(cth[0] * cth[1], 0.f);
    ab[1] = make_float2(cth[0] * eph[1].x, cth[0] * eph[1].y);
    ab[2] = make_float2(eph[0].x * cth[1], eph[0].y * cth[1]);
    ab[3] = cmul(eph[0], eph[1]);
    cd[0] = make_float2(cth[2] * cth[3], 0.f);
    cd[1] = make_float2(cth[2] * eph[3].x, cth[2] * eph[3].y);
    cd[2] = make_float2(eph[2].x * cth[3], eph[2].y * cth[3]);
    cd[3] = cmul(eph[2], eph[3]);

    // amp[s] = sum_k U[s][k] * psi[k], packed (ar,ai) accumulators
    ull A[DIM];
#pragma unroll
    for (int s = 0; s < DIM; s++) A[s] = 0ull;

#pragma unroll
    for (int i = 0; i < 4; i++) {
#pragma unroll
        for (int j = 0; j < 4; j++) {
            float2 pv = cmul(ab[i], cd[j]);        // psi[k], k = i*4+j
            ull P  = pk2(pv.x, pv.y);              // (pr, pi)
            ull Ps = pk2(pv.y, pv.x);              // (pi, pr)
            const ulonglong2* row = &sU[(i * 4 + j) * DIM];
#pragma unroll
            for (int s = 0; s < DIM; s++) {
                ulonglong2 u = row[s];             // (re,re), (-im,im)
                A[s] = ffma2(u.x, P,  A[s]);       // (+re*pr, +re*pi)
                A[s] = ffma2(u.y, Ps, A[s]);       // (-im*pi, +im*pr)
            }
        }
    }

    // probabilities + Walsh sign tree for the 4 <Z> values
    float pr[DIM];
#pragma unroll
    for (int s = 0; s < DIM; s++) {
        float ar, ai;
        upk2(A[s], ar, ai);
        pr[s] = fmaf(ar, ar, ai * ai);
    }

    float e1[8], o1[8];
#pragma unroll
    for (int t = 0; t < 8; t++) { e1[t] = pr[2*t] + pr[2*t+1]; o1[t] = pr[2*t] - pr[2*t+1]; }
    float z3 = ((o1[0]+o1[1]) + (o1[2]+o1[3])) + ((o1[4]+o1[5]) + (o1[6]+o1[7]));
    float e2[4], o2[4];
#pragma unroll
    for (int t = 0; t < 4; t++) { e2[t] = e1[2*t] + e1[2*t+1]; o2[t] = e1[2*t] - e1[2*t+1]; }
    float z2 = (o2[0]+o2[1]) + (o2[2]+o2[3]);
    float e3[2], o3[2];
#pragma unroll
    for (int t = 0; t < 2; t++) { e3[t] = e2[2*t] + e2[2*t+1]; o3[t] = e2[2*t] - e2[2*t+1]; }
    float z1 = o3[0] + o3[1];
    float z0 = e3[0] - e3[1];

    reinterpret_cast<float4*>(out)[idx] = make_float4(z0, z1, z2, z3);
}

extern "C" void kernel_launch(void* const* d_in, const int* in_sizes, int n_in,
                              void* d_out, int out_size) {
    const float* x = (const float*)d_in[0];
    const float* w = (const float*)d_in[1];
    float* out = (float*)d_out;

    k_build_U<<<1, 256>>>(w);

    int blocks = (TOTALc + 255) / 256;   // 2017
    k_qcnn<<<blocks, 256>>>(x, out);
}

// round 4
// speedup vs baseline: 1.5815x; 1.3112x over previous
#include <cuda_runtime.h>

// QCNN_58025008169535
// x: [32,128,128,3] f32, w: [4,4,3] f32 -> out: [32, 127*127, 4] f32

#define DIM 16
#define NL 4
#define NQ 4

static constexpr int Bc = 32, Hc = 128, Wc = 128;
static constexpr int PHc = Hc - 1, PWc = Wc - 1;
static constexpr int Pc = PHc * PWc;          // 16129
static constexpr int TOTALc = Bc * Pc;        // 516128
static constexpr int HALFc = TOTALc / 2;      // 258064

typedef unsigned long long ull;

// Packed U, column-major [k][s]: (re,re) and (-im,im) of U[s][k]
__device__ ulonglong2 g_Upk[DIM * DIM];

__device__ __forceinline__ float2 cmul(float2 a, float2 b) {
    return make_float2(fmaf(a.x, b.x, -a.y * b.y), fmaf(a.x, b.y, a.y * b.x));
}
__device__ __forceinline__ float2 cadd(float2 a, float2 b) {
    return make_float2(a.x + b.x, a.y + b.y);
}
__device__ __forceinline__ ull pk2(float lo, float hi) {
    ull r; asm("mov.b64 %0, {%1,%2};" : "=l"(r) : "f"(lo), "f"(hi)); return r;
}
__device__ __forceinline__ void upk2(ull v, float& lo, float& hi) {
    asm("mov.b64 {%0,%1}, %2;" : "=f"(lo), "=f"(hi) : "l"(v));
}
__device__ __forceinline__ ull ffma2(ull a, ull b, ull c) {
    ull d; asm("fma.rn.f32x2 %0, %1, %2, %3;" : "=l"(d) : "l"(a), "l"(b), "l"(c));
    return d;
}

// ---------------------------------------------------------------------------
// Kernel 1 (256 threads): build the variational unitary in parallel.
// ---------------------------------------------------------------------------
__global__ void k_build_U(const float* __restrict__ w) {
    __shared__ float2 sg[16][4];         // gate (h*4+q): u00,u01,u10,u11
    __shared__ float2 sM[4][DIM][DIM];   // layer matrices (CZ folded)
    __shared__ float2 sT[2][DIM][DIM];

    int tid = threadIdx.x;

    if (tid < 16) {
        float wx = w[tid * 3 + 0];
        float wy = w[tid * 3 + 1];
        float wz = w[tid * 3 + 2];
        float cx, sx, cy, sy, cz, sz;
        sincosf(0.5f * wx, &sx, &cx);
        sincosf(0.5f * wy, &sy, &cy);
        sincosf(0.5f * wz, &sz, &cz);
        // Ry(wy)*Rx(wx)
        float2 m00 = make_float2(cy * cx,  sy * sx);
        float2 m01 = make_float2(-sy * cx, -cy * sx);
        float2 m10 = make_float2(sy * cx,  -cy * sx);
        float2 m11 = make_float2(cy * cx,  -sy * sx);
        // Rz(wz) on rows
        float2 e0 = make_float2(cz, -sz);
        float2 e1 = make_float2(cz,  sz);
        sg[tid][0] = cmul(e0, m00);
        sg[tid][1] = cmul(e0, m01);
        sg[tid][2] = cmul(e1, m10);
        sg[tid][3] = cmul(e1, m11);
    }
    __syncthreads();

    // Layer matrices: 1024 elements, 4 per thread
#pragma unroll
    for (int r = 0; r < 4; r++) {
        int e = tid + 256 * r;
        int h = e >> 8;
        int st = e & 255;
        int s = st >> 4, t = st & 15;
        float2 prod = make_float2(1.f, 0.f);
#pragma unroll
        for (int q = 0; q < NQ; q++) {
            int sb = (s >> (3 - q)) & 1;
            int tb = (t >> (3 - q)) & 1;
            prod = cmul(prod, sg[h * 4 + q][sb * 2 + tb]);
        }
        bool neg = (((s & 12) == 12) ^ ((s & 3) == 3)) ^ ((s & 6) == 6);
        if (neg) { prod.x = -prod.x; prod.y = -prod.y; }
        sM[h][s][t] = prod;
    }
    __syncthreads();

    {
        int s = tid >> 4, t = tid & 15;
        float2 a1 = make_float2(0.f, 0.f);
        float2 a2 = make_float2(0.f, 0.f);
#pragma unroll
        for (int k = 0; k < DIM; k++) {
            a1 = cadd(a1, cmul(sM[1][s][k], sM[0][k][t]));
            a2 = cadd(a2, cmul(sM[3][s][k], sM[2][k][t]));
        }
        sT[0][s][t] = a1;
        sT[1][s][t] = a2;
    }
    __syncthreads();

    {
        int s = tid >> 4, t = tid & 15;
        float2 u = make_float2(0.f, 0.f);
#pragma unroll
        for (int k = 0; k < DIM; k++)
            u = cadd(u, cmul(sT[1][s][k], sT[0][k][t]));
        ulonglong2 pkd;
        pkd.x = pk2(u.x, u.x);
        pkd.y = pk2(-u.y, u.y);
        g_Upk[t * DIM + s] = pkd;   // column-major [k][s]
    }
}

// ---------------------------------------------------------------------------
// Kernel 2: TWO patches per thread (amortize U smem traffic), FFMA2 matvec,
// MUFU sincos encoding.
// ---------------------------------------------------------------------------
struct Enc { float2 ab[4]; float2 cd[4]; };

__device__ __forceinline__ void encode(const float* __restrict__ x, int idx, Enc& e) {
    int b  = idx / Pc;
    int p  = idx - b * Pc;
    int ph = p / PWc;
    int pw = p - ph * PWc;

    float  cth[NQ];
    float2 eph[NQ];
#pragma unroll
    for (int n = 0; n < NQ; n++) {
        int dy = n >> 1, dx = n & 1;
        const float* px = x + ((((b * Hc) + (ph + dy)) * Wc + (pw + dx)) * 3);
        float l1 = px[1];
        float l2 = px[2];
        float sb, cb, sp, cp;
        __sincosf(1.57079632679489662f * l1, &sb, &cb);
        __sincosf(3.14159265358979323f * l2, &sp, &cp);
        cth[n] = cb;
        eph[n] = make_float2(sb * cp, sb * sp);
    }
    e.ab[0] = make_float2(cth[0] * cth[1], 0.f);
    e.ab[1] = make_float2(cth[0] * eph[1].x, cth[0] * eph[1].y);
    e.ab[2] = make_float2(eph[0].x * cth[1], eph[0].y * cth[1]);
    e.ab[3] = cmul(eph[0], eph[1]);
    e.cd[0] = make_float2(cth[2] * cth[3], 0.f);
    e.cd[1] = make_float2(cth[2] * eph[3].x, cth[2] * eph[3].y);
    e.cd[2] = make_float2(eph[2].x * cth[3], eph[2].y * cth[3]);
    e.cd[3] = cmul(eph[2], eph[3]);
}

__device__ __forceinline__ void finish(const ull* __restrict__ A,
                                       float* __restrict__ out, int idx) {
    float pr[DIM];
#pragma unroll
    for (int s = 0; s < DIM; s++) {
        ull sq = ffma2(A[s], A[s], 0ull);   // (ar^2, ai^2)
        float a, b2;
        upk2(sq, a, b2);
        pr[s] = a + b2;
    }
    float e1[8], o1[8];
#pragma unroll
    for (int t = 0; t < 8; t++) { e1[t] = pr[2*t] + pr[2*t+1]; o1[t] = pr[2*t] - pr[2*t+1]; }
    float z3 = ((o1[0]+o1[1]) + (o1[2]+o1[3])) + ((o1[4]+o1[5]) + (o1[6]+o1[7]));
    float e2[4], o2[4];
#pragma unroll
    for (int t = 0; t < 4; t++) { e2[t] = e1[2*t] + e1[2*t+1]; o2[t] = e1[2*t] - e1[2*t+1]; }
    float z2 = (o2[0]+o2[1]) + (o2[2]+o2[3]);
    float e3[2], o3[2];
#pragma unroll
    for (int t = 0; t < 2; t++) { e3[t] = e2[2*t] + e2[2*t+1]; o3[t] = e2[2*t] - e2[2*t+1]; }
    float z1 = o3[0] + o3[1];
    float z0 = e3[0] - e3[1];

    reinterpret_cast<float4*>(out)[idx] = make_float4(z0, z1, z2, z3);
}

__global__ void __launch_bounds__(128, 4)
k_qcnn(const float* __restrict__ x, float* __restrict__ out) {
    __shared__ ulonglong2 sU[DIM * DIM];   // [k][s], 4KB
    for (int i = threadIdx.x; i < DIM * DIM; i += 128) sU[i] = g_Upk[i];
    __syncthreads();

    int t = blockIdx.x * 128 + threadIdx.x;
    if (t >= HALFc) return;
    int idx0 = t;
    int idx1 = t + HALFc;

    Enc e0, e1;
    encode(x, idx0, e0);
    encode(x, idx1, e1);

    ull A0[DIM], A1[DIM];
#pragma unroll
    for (int s = 0; s < DIM; s++) { A0[s] = 0ull; A1[s] = 0ull; }

#pragma unroll
    for (int i = 0; i < 4; i++) {
#pragma unroll
        for (int j = 0; j < 4; j++) {
            float2 p0 = cmul(e0.ab[i], e0.cd[j]);
            float2 p1 = cmul(e1.ab[i], e1.cd[j]);
            ull P0 = pk2(p0.x, p0.y), Q0 = pk2(p0.y, p0.x);
            ull P1 = pk2(p1.x, p1.y), Q1 = pk2(p1.y, p1.x);
            const ulonglong2* row = &sU[(i * 4 + j) * DIM];
#pragma unroll
            for (int s = 0; s < DIM; s++) {
                ulonglong2 u = row[s];           // (re,re), (-im,im)
                A0[s] = ffma2(u.x, P0, A0[s]);
                A0[s] = ffma2(u.y, Q0, A0[s]);
                A1[s] = ffma2(u.x, P1, A1[s]);
                A1[s] = ffma2(u.y, Q1, A1[s]);
            }
        }
    }

    finish(A0, out, idx0);
    finish(A1, out, idx1);
}

extern "C" void kernel_launch(void* const* d_in, const int* in_sizes, int n_in,
                              void* d_out, int out_size) {
    const float* x = (const float*)d_in[0];
    const float* w = (const float*)d_in[1];
    float* out = (float*)d_out;

    k_build_U<<<1, 256>>>(w);

    int blocks = (HALFc + 127) / 128;   // 2017
    k_qcnn<<<blocks, 128>>>(x, out);
}